// round 14
// baseline (speedup 1.0000x reference)
#include <cuda_runtime.h>
#include <cuda_bf16.h>
#include <stdint.h>

// B=8, T=2048, D=768, QKV_OUT=2304. Single-head attention over full 768 dims,
// scale 1/sqrt(64)=0.125. NT mma.sync bf16 split hi/lo 3-pass GEMMs reading
// pre-split gmem planes via cp.async; R10 execution shape (256thr, 2 CTA/SM,
// single 40KB static buffer, warp tile 64x32, ldmatrix).
#define BT 16384
#define DIM 768
#define QKVO 2304
#define SEQ 2048
#define NB 8
#define SCALE 0.125f

// fp32 scratch
__device__ float g_scores[(size_t)NB * SEQ * SEQ];   // 8 x 2048 x 2048
__device__ float g_v[(size_t)BT * DIM];              // V fp32 (pre-transpose)
// bf16 hi/lo planes
__device__ __nv_bfloat16 g_xh[(size_t)BT * DIM],  g_xl[(size_t)BT * DIM];
__device__ __nv_bfloat16 g_qh[(size_t)BT * DIM],  g_ql[(size_t)BT * DIM];
__device__ __nv_bfloat16 g_kh[(size_t)BT * DIM],  g_kl[(size_t)BT * DIM];
__device__ __nv_bfloat16 g_vth[(size_t)NB * DIM * SEQ], g_vtl[(size_t)NB * DIM * SEQ];
__device__ __nv_bfloat16 g_ph[(size_t)NB * SEQ * SEQ],  g_pl[(size_t)NB * SEQ * SEQ];
__device__ __nv_bfloat16 g_oh[(size_t)BT * DIM],  g_ol[(size_t)BT * DIM];
__device__ __nv_bfloat16 g_wqh[(size_t)QKVO * DIM], g_wql[(size_t)QKVO * DIM];
__device__ __nv_bfloat16 g_woh[(size_t)DIM * DIM],  g_wol[(size_t)DIM * DIM];

// split pair (x -> lower k, y -> upper k) into packed hi word + lo word
__device__ __forceinline__ void split2(float x, float y, uint32_t& h, uint32_t& l) {
    __nv_bfloat16 hx = __float2bfloat16(x), hy = __float2bfloat16(y);
    __nv_bfloat16 lx = __float2bfloat16(x - __bfloat162float(hx));
    __nv_bfloat16 ly = __float2bfloat16(y - __bfloat162float(hy));
    h = ((uint32_t)__bfloat16_as_ushort(hy) << 16) | (uint32_t)__bfloat16_as_ushort(hx);
    l = ((uint32_t)__bfloat16_as_ushort(ly) << 16) | (uint32_t)__bfloat16_as_ushort(lx);
}
__device__ __forceinline__ void mma_bf16(float* d, const uint32_t* a, const uint32_t* b) {
    asm volatile(
        "mma.sync.aligned.m16n8k16.row.col.f32.bf16.bf16.f32 "
        "{%0,%1,%2,%3}, {%4,%5,%6,%7}, {%8,%9}, {%0,%1,%2,%3};"
        : "+f"(d[0]), "+f"(d[1]), "+f"(d[2]), "+f"(d[3])
        : "r"(a[0]), "r"(a[1]), "r"(a[2]), "r"(a[3]), "r"(b[0]), "r"(b[1]));
}
#define LDSM_X4(r0, r1, r2, r3, addr) \
    asm volatile("ldmatrix.sync.aligned.m8n8.x4.shared.b16 {%0,%1,%2,%3}, [%4];" \
        : "=r"(r0), "=r"(r1), "=r"(r2), "=r"(r3) : "r"(addr))
#define CP16(dst, src) \
    asm volatile("cp.async.ca.shared.global [%0], [%1], 16;" :: "r"(dst), "l"(src))
#define CPCOMMIT() asm volatile("cp.async.commit_group;")
#define CPWAIT0() asm volatile("cp.async.wait_group 0;")

// Plane layout in smem: rows of 80B (32 data bf16 + pad) per surface.
#define PLANE 10240
#define ROWB 80

// ---------------------------------------------------------------------------
// NT GEMM on pre-split planes: C = alpha*A@B^T (+bias). BM=BN=128, BK=32.
// 256 thr = 8 warps (2M x 4N), warp tile 64x32. Single buffer, 2 CTA/SM.
// OMODE 0: fp32 C (o0). OMODE 1: plane C (o0=hi, o1=lo).
// OMODE 2: qkv split -> Q planes (o0,o1), K planes (o2,o3), V fp32 (o4).
// ---------------------------------------------------------------------------
template<int OMODE>
__global__ __launch_bounds__(256, 2)
void gemm_pl(const __nv_bfloat16* __restrict__ Ah, const __nv_bfloat16* __restrict__ Al,
             const __nv_bfloat16* __restrict__ Bh, const __nv_bfloat16* __restrict__ Bl,
             void* o0, void* o1, void* o2, void* o3, void* o4,
             const float* __restrict__ bias,
             int K, int lda, int ldb, int ldc, float alpha,
             long long sA, long long sB, long long sC)
{
    __shared__ __align__(16) char smem[4 * PLANE];

    const int tid = threadIdx.x;
    const int lane = tid & 31, wid = tid >> 5;
    const int wm = (wid >> 2) * 64;     // 0 / 64
    const int wn = (wid & 3) * 32;      // 0/32/64/96
    const int lr = lane >> 2, lc = lane & 3;
    const uint32_t sbase = (uint32_t)__cvta_generic_to_shared(smem);
    const int lm_i = lane & 7, lm_j = lane >> 3;
    const uint32_t laneoff =
        (uint32_t)((lm_i + (lm_j & 1) * 8) * ROWB + (lm_j >> 1) * 16);

    // loader: 4 surfaces x 128 rows = 512 rows; 2 rows/thread, 64B per row.
    const int l_surf = tid >> 6;            // 0=Ah 1=Al 2=Bh 3=Bl
    const int l_r0 = (tid & 63) * 2;
    const __nv_bfloat16* lbase;
    int ldg;
    if (l_surf < 2) {
        lbase = (l_surf ? Al : Ah) + (size_t)blockIdx.z * sA
              + (size_t)(blockIdx.y * 128 + l_r0) * lda;
        ldg = lda;
    } else {
        lbase = (l_surf == 3 ? Bl : Bh) + (size_t)blockIdx.z * sB
              + (size_t)(blockIdx.x * 128 + l_r0) * ldb;
        ldg = ldb;
    }
    const uint32_t l_dst = sbase + (uint32_t)(l_surf * PLANE + l_r0 * ROWB);

    float acc[4][4][4];
#pragma unroll
    for (int i = 0; i < 4; i++)
#pragma unroll
        for (int j = 0; j < 4; j++)
#pragma unroll
            for (int q = 0; q < 4; q++) acc[i][j][q] = 0.0f;

    const int nc = K >> 5;
    for (int c = 0; c < nc; c++) {
        __syncthreads();   // previous compute done before overwrite
        {
            const __nv_bfloat16* s = lbase + c * 32;
#pragma unroll
            for (int q = 0; q < 4; q++) {
                CP16(l_dst + q * 16, s + q * 8);
                CP16(l_dst + ROWB + q * 16, s + ldg + q * 8);
            }
            CPCOMMIT();
            CPWAIT0();
        }
        __syncthreads();

#pragma unroll
        for (int ks = 0; ks < 2; ks++) {
            const uint32_t kb = (uint32_t)(ks * 32);
            uint32_t bh[4][2], bl[4][2];
#pragma unroll
            for (int q = 0; q < 2; q++) {
                uint32_t ba = sbase + 2 * PLANE
                            + (uint32_t)((wn + q * 16) * ROWB) + laneoff + kb;
                uint32_t r0, r1, r2, r3;
                LDSM_X4(r0, r1, r2, r3, ba);
                bh[q * 2][0] = r0; bh[q * 2 + 1][0] = r1;
                bh[q * 2][1] = r2; bh[q * 2 + 1][1] = r3;
                LDSM_X4(r0, r1, r2, r3, ba + PLANE);
                bl[q * 2][0] = r0; bl[q * 2 + 1][0] = r1;
                bl[q * 2][1] = r2; bl[q * 2 + 1][1] = r3;
            }
#pragma unroll
            for (int im = 0; im < 4; im++) {
                uint32_t aa = sbase + (uint32_t)((wm + im * 16) * ROWB)
                            + laneoff + kb;
                uint32_t ah[4], al[4];
                LDSM_X4(ah[0], ah[1], ah[2], ah[3], aa);
                LDSM_X4(al[0], al[1], al[2], al[3], aa + PLANE);
#pragma unroll
                for (int jn = 0; jn < 4; jn++) {
                    mma_bf16(acc[im][jn], ah, bh[jn]);   // hi*hi
                    mma_bf16(acc[im][jn], ah, bl[jn]);   // hi*lo
                    mma_bf16(acc[im][jn], al, bh[jn]);   // lo*hi
                }
            }
        }
    }

    // ---- epilogue ----
#pragma unroll
    for (int im = 0; im < 4; im++) {
        const int gr = blockIdx.y * 128 + wm + im * 16 + lr;
#pragma unroll
        for (int jn = 0; jn < 4; jn++) {
            const int ct = wn + jn * 8 + 2 * lc;
            float v0 = alpha * acc[im][jn][0];
            float v1 = alpha * acc[im][jn][1];
            float v2 = alpha * acc[im][jn][2];
            float v3 = alpha * acc[im][jn][3];

            if (OMODE == 0) {
                const int gc = blockIdx.x * 128 + ct;
                if (bias) { v0 += bias[gc]; v1 += bias[gc + 1];
                            v2 += bias[gc]; v3 += bias[gc + 1]; }
                float* C = (float*)o0 + (size_t)blockIdx.z * sC;
                *(float2*)(C + (size_t)gr * ldc + gc) = make_float2(v0, v1);
                *(float2*)(C + (size_t)(gr + 8) * ldc + gc) = make_float2(v2, v3);
            } else if (OMODE == 1) {
                const int gc = blockIdx.x * 128 + ct;
                __nv_bfloat16* Ch = (__nv_bfloat16*)o0 + (size_t)blockIdx.z * sC;
                __nv_bfloat16* Cl = (__nv_bfloat16*)o1 + (size_t)blockIdx.z * sC;
                uint32_t h, l;
                split2(v0, v1, h, l);
                *(uint32_t*)((char*)Ch + ((size_t)gr * ldc + gc) * 2) = h;
                *(uint32_t*)((char*)Cl + ((size_t)gr * ldc + gc) * 2) = l;
                split2(v2, v3, h, l);
                *(uint32_t*)((char*)Ch + ((size_t)(gr + 8) * ldc + gc) * 2) = h;
                *(uint32_t*)((char*)Cl + ((size_t)(gr + 8) * ldc + gc) * 2) = l;
            } else {
                const int reg = blockIdx.x / 6;                   // 0=Q 1=K 2=V
                const int gc = (blockIdx.x - reg * 6) * 128 + ct;
                const int bcol = reg * 768 + gc;
                v0 += bias[bcol]; v1 += bias[bcol + 1];
                v2 += bias[bcol]; v3 += bias[bcol + 1];
                if (reg == 2) {
                    float* Vc = (float*)o4;
                    *(float2*)(Vc + (size_t)gr * 768 + gc) = make_float2(v0, v1);
                    *(float2*)(Vc + (size_t)(gr + 8) * 768 + gc) = make_float2(v2, v3);
                } else {
                    __nv_bfloat16* Ph = (__nv_bfloat16*)(reg == 0 ? o0 : o2);
                    __nv_bfloat16* Pl = (__nv_bfloat16*)(reg == 0 ? o1 : o3);
                    uint32_t h, l;
                    split2(v0, v1, h, l);
                    *(uint32_t*)((char*)Ph + ((size_t)gr * 768 + gc) * 2) = h;
                    *(uint32_t*)((char*)Pl + ((size_t)gr * 768 + gc) * 2) = l;
                    split2(v2, v3, h, l);
                    *(uint32_t*)((char*)Ph + ((size_t)(gr + 8) * 768 + gc) * 2) = h;
                    *(uint32_t*)((char*)Pl + ((size_t)(gr + 8) * 768 + gc) * 2) = l;
                }
            }
        }
    }
}

// ---------------------------------------------------------------------------
// Elementwise fp32 -> hi/lo planes. n4 = element count / 4.
// ---------------------------------------------------------------------------
__global__ __launch_bounds__(256)
void convert_pl(const float* __restrict__ src,
                __nv_bfloat16* __restrict__ dh, __nv_bfloat16* __restrict__ dl,
                int n4)
{
    int i = blockIdx.x * 256 + threadIdx.x;
    if (i < n4) {
        float4 v = ((const float4*)src)[i];
        uint32_t h0, l0, h1, l1;
        split2(v.x, v.y, h0, l0);
        split2(v.z, v.w, h1, l1);
        ((uint2*)dh)[i] = make_uint2(h0, h1);
        ((uint2*)dl)[i] = make_uint2(l0, l1);
    }
}

// ---------------------------------------------------------------------------
// Batched 32x32 transpose + split: dst planes[c][r] = split(src[r][c]).
// ---------------------------------------------------------------------------
__global__ __launch_bounds__(256)
void transpose_pl(const float* __restrict__ src,
                  __nv_bfloat16* __restrict__ dh, __nv_bfloat16* __restrict__ dl,
                  int lds, int ldd, long long sS, long long sD)
{
    __shared__ float t[32][33];
    src += (size_t)blockIdx.z * sS;
    dh += (size_t)blockIdx.z * sD;
    dl += (size_t)blockIdx.z * sD;
    int r0 = blockIdx.y * 32, c0 = blockIdx.x * 32;
    int tx = threadIdx.x & 31, ty = threadIdx.x >> 5;   // 32 x 8
#pragma unroll
    for (int i = ty; i < 32; i += 8)
        t[i][tx] = src[(size_t)(r0 + i) * lds + c0 + tx];
    __syncthreads();
#pragma unroll
    for (int j = ty; j < 32; j += 8) {
        if (tx < 16) {
            float a = t[2 * tx][j], b = t[2 * tx + 1][j];
            uint32_t h, l;
            split2(a, b, h, l);
            size_t off = ((size_t)(c0 + j) * ldd + r0) * 2 + tx * 4;
            *(uint32_t*)((char*)dh + off) = h;
            *(uint32_t*)((char*)dl + off) = l;
        }
    }
}

// ---------------------------------------------------------------------------
// Row softmax: reads fp32 scores, writes P hi/lo planes. 1 block / row.
// ---------------------------------------------------------------------------
__global__ __launch_bounds__(256)
void softmax_pl(const float* __restrict__ S,
                __nv_bfloat16* __restrict__ ph, __nv_bfloat16* __restrict__ pl)
{
    __shared__ float red[8];
    int tid = threadIdx.x;
    const float* row = S + (size_t)blockIdx.x * SEQ;

    float4 v0 = *(const float4*)(row + tid * 4);
    float4 v1 = *(const float4*)(row + 1024 + tid * 4);

    float mx = fmaxf(fmaxf(fmaxf(v0.x, v0.y), fmaxf(v0.z, v0.w)),
                     fmaxf(fmaxf(v1.x, v1.y), fmaxf(v1.z, v1.w)));
#pragma unroll
    for (int off = 16; off > 0; off >>= 1)
        mx = fmaxf(mx, __shfl_xor_sync(0xffffffffu, mx, off));
    if ((tid & 31) == 0) red[tid >> 5] = mx;
    __syncthreads();
    if (tid < 32) {
        float t = (tid < 8) ? red[tid] : -1e30f;
#pragma unroll
        for (int off = 4; off > 0; off >>= 1)
            t = fmaxf(t, __shfl_xor_sync(0xffffffffu, t, off));
        if (tid == 0) red[0] = t;
    }
    __syncthreads();
    mx = red[0];

    v0.x = __expf(v0.x - mx); v0.y = __expf(v0.y - mx);
    v0.z = __expf(v0.z - mx); v0.w = __expf(v0.w - mx);
    v1.x = __expf(v1.x - mx); v1.y = __expf(v1.y - mx);
    v1.z = __expf(v1.z - mx); v1.w = __expf(v1.w - mx);

    float sm_ = v0.x + v0.y + v0.z + v0.w + v1.x + v1.y + v1.z + v1.w;
#pragma unroll
    for (int off = 16; off > 0; off >>= 1)
        sm_ += __shfl_xor_sync(0xffffffffu, sm_, off);
    if ((tid & 31) == 0) red[tid >> 5] = sm_;
    __syncthreads();
    if (tid < 32) {
        float t = (tid < 8) ? red[tid] : 0.0f;
#pragma unroll
        for (int off = 4; off > 0; off >>= 1)
            t += __shfl_xor_sync(0xffffffffu, t, off);
        if (tid == 0) red[0] = t;
    }
    __syncthreads();
    float inv = 1.0f / red[0];

    v0.x *= inv; v0.y *= inv; v0.z *= inv; v0.w *= inv;
    v1.x *= inv; v1.y *= inv; v1.z *= inv; v1.w *= inv;

    uint32_t h0, l0, h1, l1;
    uint2* ph2 = (uint2*)(ph + (size_t)blockIdx.x * SEQ);
    uint2* pl2 = (uint2*)(pl + (size_t)blockIdx.x * SEQ);
    split2(v0.x, v0.y, h0, l0);
    split2(v0.z, v0.w, h1, l1);
    ph2[tid] = make_uint2(h0, h1);
    pl2[tid] = make_uint2(l0, l1);
    split2(v1.x, v1.y, h0, l0);
    split2(v1.z, v1.w, h1, l1);
    ph2[256 + tid] = make_uint2(h0, h1);
    pl2[256 + tid] = make_uint2(l0, l1);
}

// ---------------------------------------------------------------------------
extern "C" void kernel_launch(void* const* d_in, const int* in_sizes, int n_in,
                              void* d_out, int out_size)
{
    const float* x     = (const float*)d_in[0];   // [8,2048,768]
    const float* w_qkv = (const float*)d_in[1];   // [768,2304]
    const float* b_qkv = (const float*)d_in[2];   // [2304]
    const float* w_out = (const float*)d_in[3];   // [768,768]
    const float* b_out = (const float*)d_in[4];   // [768]
    float* out = (float*)d_out;                   // [8,2048,768]

    float *sc_p, *v_p;
    __nv_bfloat16 *xh, *xl, *qh, *ql, *kh, *kl, *vth, *vtl, *pph, *ppl,
                  *oh, *ol, *wqh, *wql, *woh, *wol;
    cudaGetSymbolAddress((void**)&sc_p, g_scores);
    cudaGetSymbolAddress((void**)&v_p, g_v);
    cudaGetSymbolAddress((void**)&xh, g_xh);   cudaGetSymbolAddress((void**)&xl, g_xl);
    cudaGetSymbolAddress((void**)&qh, g_qh);   cudaGetSymbolAddress((void**)&ql, g_ql);
    cudaGetSymbolAddress((void**)&kh, g_kh);   cudaGetSymbolAddress((void**)&kl, g_kl);
    cudaGetSymbolAddress((void**)&vth, g_vth); cudaGetSymbolAddress((void**)&vtl, g_vtl);
    cudaGetSymbolAddress((void**)&pph, g_ph);  cudaGetSymbolAddress((void**)&ppl, g_pl);
    cudaGetSymbolAddress((void**)&oh, g_oh);   cudaGetSymbolAddress((void**)&ol, g_ol);
    cudaGetSymbolAddress((void**)&wqh, g_wqh); cudaGetSymbolAddress((void**)&wql, g_wql);
    cudaGetSymbolAddress((void**)&woh, g_woh); cudaGetSymbolAddress((void**)&wol, g_wol);

    const long long sQ  = (long long)SEQ * DIM;
    const long long sS  = (long long)SEQ * SEQ;
    const long long sVT = (long long)DIM * SEQ;

    // 0) pre-split inputs
    convert_pl<<<(BT * DIM / 4 + 255) / 256, 256>>>(x, xh, xl, BT * DIM / 4);
    transpose_pl<<<dim3(QKVO / 32, DIM / 32, 1), 256>>>(w_qkv, wqh, wql, QKVO, DIM, 0, 0);
    transpose_pl<<<dim3(DIM / 32, DIM / 32, 1), 256>>>(w_out, woh, wol, DIM, DIM, 0, 0);

    // 1) QKV projection -> Q/K planes + V fp32
    gemm_pl<2><<<dim3(QKVO / 128, BT / 128, 1), 256>>>(
        xh, xl, wqh, wql, qh, ql, kh, kl, v_p, b_qkv,
        DIM, DIM, DIM, 0, 1.0f, 0, 0, 0);

    // 1b) V -> vT planes per batch
    transpose_pl<<<dim3(DIM / 32, SEQ / 32, NB), 256>>>(
        v_p, vth, vtl, DIM, SEQ, (long long)SEQ * DIM, sVT);

    // 2) S = 0.125 * Q @ K^T -> fp32 scores
    gemm_pl<0><<<dim3(SEQ / 128, SEQ / 128, NB), 256>>>(
        qh, ql, kh, kl, sc_p, nullptr, nullptr, nullptr, nullptr, nullptr,
        DIM, DIM, DIM, SEQ, SCALE, sQ, sQ, sS);

    // 3) softmax -> P planes
    softmax_pl<<<NB * SEQ, 256>>>(sc_p, pph, ppl);

    // 4) O = P @ vT^T -> att planes
    gemm_pl<1><<<dim3(DIM / 128, SEQ / 128, NB), 256>>>(
        pph, ppl, vth, vtl, oh, ol, nullptr, nullptr, nullptr, nullptr,
        SEQ, SEQ, SEQ, DIM, 1.0f, sS, sVT, sQ);

    // 5) out = att @ w_out^T + b_out -> fp32
    gemm_pl<0><<<dim3(DIM / 128, BT / 128, 1), 256>>>(
        oh, ol, woh, wol, out, nullptr, nullptr, nullptr, nullptr, b_out,
        DIM, DIM, DIM, DIM, 1.0f, 0, 0, 0);
}

// round 16
// speedup vs baseline: 1.7030x; 1.7030x over previous
#include <cuda_runtime.h>
#include <cuda_bf16.h>
#include <stdint.h>

// B=8, T=2048, D=768, QKV_OUT=2304. Single-head attention over full 768 dims,
// scale 1/sqrt(64)=0.125. All GEMMs NT on mma.sync bf16 (split hi/lo 3-pass),
// ldmatrix fragments, 256thr x 2CTA/SM, warp tile 64x32, BK=32, 40KB static
// smem (R10 baseline). R16: register prefetch of next chunk + bf16x2 split.
#define BT 16384
#define DIM 768
#define QKVO 2304
#define SEQ 2048
#define NB 8
#define SCALE 0.125f

__device__ float g_qkv[(size_t)BT * QKVO];          // 16384 x 2304 (q|k|v)
__device__ float g_scores[(size_t)NB * SEQ * SEQ];  // 8 x 2048 x 2048
__device__ float g_att[(size_t)BT * DIM];           // 16384 x 768
__device__ float g_wqkvT[(size_t)QKVO * DIM];       // 2304 x 768
__device__ float g_woutT[(size_t)DIM * DIM];        // 768 x 768
__device__ float g_vT[(size_t)NB * DIM * SEQ];      // 8 x 768 x 2048

// split pair (x lower-k, y upper-k) -> packed hi word, lo word.
// cvt.rn.bf16x2.f32 d, a, b packs a into upper, b into lower half (RN — same
// rounding as __float2bfloat16, so results are bit-identical to prior rounds).
__device__ __forceinline__ void split2(float x, float y, uint32_t& h, uint32_t& l) {
    asm("cvt.rn.bf16x2.f32 %0, %1, %2;" : "=r"(h) : "f"(y), "f"(x));
    float hx = __uint_as_float(h << 16);
    float hy = __uint_as_float(h & 0xFFFF0000u);
    asm("cvt.rn.bf16x2.f32 %0, %1, %2;" : "=r"(l) : "f"(y - hy), "f"(x - hx));
}
__device__ __forceinline__ void mma_bf16(float* d, const uint32_t* a, const uint32_t* b) {
    asm volatile(
        "mma.sync.aligned.m16n8k16.row.col.f32.bf16.bf16.f32 "
        "{%0,%1,%2,%3}, {%4,%5,%6,%7}, {%8,%9}, {%0,%1,%2,%3};"
        : "+f"(d[0]), "+f"(d[1]), "+f"(d[2]), "+f"(d[3])
        : "r"(a[0]), "r"(a[1]), "r"(a[2]), "r"(a[3]), "r"(b[0]), "r"(b[1]));
}
#define LDSM_X4(r0, r1, r2, r3, addr) \
    asm volatile("ldmatrix.sync.aligned.m8n8.x4.shared.b16 {%0,%1,%2,%3}, [%4];" \
        : "=r"(r0), "=r"(r1), "=r"(r2), "=r"(r3) : "r"(addr))

// Plane layout: [row][k] rows of 40 bf16 (80 B). Planes: Ah | Al | Bh | Bl.
#define PLANE 10240
#define ROWB 80

// ---------------------------------------------------------------------------
// NT GEMM: C[M,N] = alpha * A[M,K] @ B[N,K]^T (+bias). Batched via grid.z.
// BM=BN=128, BK=32. 256 threads = 8 warps (2M x 4N), warp tile 64x32.
// Single smem buffer (40KB static), 2 CTAs/SM, register prefetch of next chunk.
// ---------------------------------------------------------------------------
__global__ __launch_bounds__(256, 2)
void gemm_nt(const float* __restrict__ A, const float* __restrict__ B,
             const float* __restrict__ bias, float* __restrict__ C,
             int K, int lda, int ldb, int ldc, float alpha,
             long long sA, long long sB, long long sC)
{
    __shared__ __align__(16) char smem[4 * PLANE];

    const int tid = threadIdx.x;
    const int lane = tid & 31;
    const int wid = tid >> 5;
    const int wm = (wid >> 2) * 64;     // 0 / 64
    const int wn = (wid & 3) * 32;      // 0/32/64/96
    const int lr = lane >> 2;           // 0..7
    const int lc = lane & 3;            // 0..3

    const uint32_t sbase = (uint32_t)__cvta_generic_to_shared(smem);
    const int lm_i = lane & 7, lm_j = lane >> 3;
    const uint32_t laneoff =
        (uint32_t)((lm_i + (lm_j & 1) * 8) * ROWB + (lm_j >> 1) * 16);

    const float* Ap = A + (size_t)blockIdx.z * sA + (size_t)blockIdx.y * 128 * lda;
    const float* Bp = B + (size_t)blockIdx.z * sB + (size_t)blockIdx.x * 128 * ldb;
    float* Cb = C + (size_t)blockIdx.z * sC;

    // loader: thread -> row (0..127), col quad base (0 or 16 floats)
    const int ld_row = tid >> 1;
    const int ld_c0 = (tid & 1) * 16;
    const float* ar0 = Ap + (size_t)ld_row * lda + ld_c0;
    const float* br0 = Bp + (size_t)ld_row * ldb + ld_c0;

    float acc[4][4][4];
#pragma unroll
    for (int i = 0; i < 4; i++)
#pragma unroll
        for (int j = 0; j < 4; j++)
#pragma unroll
            for (int q = 0; q < 4; q++) acc[i][j][q] = 0.0f;

    // prefetch registers: chunk data (A 16 floats + B 16 floats)
    float4 pa[4], pb[4];
#pragma unroll
    for (int q = 0; q < 4; q++) {
        pa[q] = *(const float4*)(ar0 + q * 4);
        pb[q] = *(const float4*)(br0 + q * 4);
    }

    const int nc = K >> 5;
    for (int ch = 0; ch < nc; ch++) {
        __syncthreads();   // previous compute done before smem overwrite
        // ---- split prefetched chunk into hi/lo planes ----
        {
            char* Ah = smem;
            char* Al = smem + PLANE;
            char* Bh = smem + 2 * PLANE;
            char* Bl = smem + 3 * PLANE;
            const int wo = ld_row * ROWB + ld_c0 * 2;   // byte offset
#pragma unroll
            for (int q = 0; q < 4; q++) {
                uint2 h, l;
                split2(pa[q].x, pa[q].y, h.x, l.x);
                split2(pa[q].z, pa[q].w, h.y, l.y);
                *(uint2*)(Ah + wo + q * 8) = h;
                *(uint2*)(Al + wo + q * 8) = l;
            }
#pragma unroll
            for (int q = 0; q < 4; q++) {
                uint2 h, l;
                split2(pb[q].x, pb[q].y, h.x, l.x);
                split2(pb[q].z, pb[q].w, h.y, l.y);
                *(uint2*)(Bh + wo + q * 8) = h;
                *(uint2*)(Bl + wo + q * 8) = l;
            }
        }
        __syncthreads();

        // ---- prefetch next chunk (latency hidden behind MMAs below) ----
        if (ch + 1 < nc) {
            const float* ar = ar0 + (ch + 1) * 32;
            const float* br = br0 + (ch + 1) * 32;
#pragma unroll
            for (int q = 0; q < 4; q++) {
                pa[q] = *(const float4*)(ar + q * 4);
                pb[q] = *(const float4*)(br + q * 4);
            }
        }

        // ---- compute: 2 k16 steps ----
#pragma unroll
        for (int ks = 0; ks < 2; ks++) {
            const uint32_t kb = (uint32_t)(ks * 32);   // 16 bf16 = 32 B
            uint32_t bh[4][2], bl[4][2];
#pragma unroll
            for (int q = 0; q < 2; q++) {
                uint32_t ba = sbase + 2 * PLANE
                            + (uint32_t)((wn + q * 16) * ROWB) + laneoff + kb;
                uint32_t r0, r1, r2, r3;
                LDSM_X4(r0, r1, r2, r3, ba);
                bh[q * 2][0] = r0; bh[q * 2 + 1][0] = r1;
                bh[q * 2][1] = r2; bh[q * 2 + 1][1] = r3;
                LDSM_X4(r0, r1, r2, r3, ba + PLANE);
                bl[q * 2][0] = r0; bl[q * 2 + 1][0] = r1;
                bl[q * 2][1] = r2; bl[q * 2 + 1][1] = r3;
            }
#pragma unroll
            for (int im = 0; im < 4; im++) {
                uint32_t aa = sbase + (uint32_t)((wm + im * 16) * ROWB)
                            + laneoff + kb;
                uint32_t ah[4], al[4];
                LDSM_X4(ah[0], ah[1], ah[2], ah[3], aa);
                LDSM_X4(al[0], al[1], al[2], al[3], aa + PLANE);
#pragma unroll
                for (int jn = 0; jn < 4; jn++) {
                    mma_bf16(acc[im][jn], ah, bh[jn]);   // hi*hi
                    mma_bf16(acc[im][jn], ah, bl[jn]);   // hi*lo
                    mma_bf16(acc[im][jn], al, bh[jn]);   // lo*hi
                }
            }
        }
    }

    // ---- epilogue (verified m16n8 C mapping) ----
#pragma unroll
    for (int im = 0; im < 4; im++) {
        int r0 = blockIdx.y * 128 + wm + im * 16 + lr;
#pragma unroll
        for (int jn = 0; jn < 4; jn++) {
            int c0 = blockIdx.x * 128 + wn + jn * 8 + 2 * lc;
            float bx = 0.0f, by = 0.0f;
            if (bias) { bx = bias[c0]; by = bias[c0 + 1]; }
            float2 v0, v1;
            v0.x = alpha * acc[im][jn][0] + bx;
            v0.y = alpha * acc[im][jn][1] + by;
            v1.x = alpha * acc[im][jn][2] + bx;
            v1.y = alpha * acc[im][jn][3] + by;
            *(float2*)(Cb + (size_t)r0 * ldc + c0) = v0;
            *(float2*)(Cb + (size_t)(r0 + 8) * ldc + c0) = v1;
        }
    }
}

// ---------------------------------------------------------------------------
// Batched strided 32x32 tiled transpose: dst[c][r] = src[r][c].
// ---------------------------------------------------------------------------
__global__ __launch_bounds__(256)
void transpose_kernel(const float* __restrict__ src, float* __restrict__ dst,
                      int lds, int ldd, long long sS, long long sD)
{
    __shared__ float t[32][33];
    src += (size_t)blockIdx.z * sS;
    dst += (size_t)blockIdx.z * sD;
    int r0 = blockIdx.y * 32, c0 = blockIdx.x * 32;
    int tx = threadIdx.x & 31, ty = threadIdx.x >> 5;   // 32 x 8
#pragma unroll
    for (int i = ty; i < 32; i += 8)
        t[i][tx] = src[(size_t)(r0 + i) * lds + c0 + tx];
    __syncthreads();
#pragma unroll
    for (int i = ty; i < 32; i += 8)
        dst[(size_t)(c0 + i) * ldd + r0 + tx] = t[tx][i];
}

// ---------------------------------------------------------------------------
// Row softmax in place: 16384 rows x 2048 cols. One block (256 thr) per row.
// ---------------------------------------------------------------------------
__global__ __launch_bounds__(256)
void softmax_kernel(float* __restrict__ S)
{
    __shared__ float red[8];
    int tid = threadIdx.x;
    float* row = S + (size_t)blockIdx.x * SEQ;

    float4 v0 = *(const float4*)(row + tid * 4);
    float4 v1 = *(const float4*)(row + 1024 + tid * 4);

    float mx = fmaxf(fmaxf(fmaxf(v0.x, v0.y), fmaxf(v0.z, v0.w)),
                     fmaxf(fmaxf(v1.x, v1.y), fmaxf(v1.z, v1.w)));
#pragma unroll
    for (int off = 16; off > 0; off >>= 1)
        mx = fmaxf(mx, __shfl_xor_sync(0xffffffffu, mx, off));
    if ((tid & 31) == 0) red[tid >> 5] = mx;
    __syncthreads();
    if (tid < 32) {
        float t = (tid < 8) ? red[tid] : -1e30f;
#pragma unroll
        for (int off = 4; off > 0; off >>= 1)
            t = fmaxf(t, __shfl_xor_sync(0xffffffffu, t, off));
        if (tid == 0) red[0] = t;
    }
    __syncthreads();
    mx = red[0];

    v0.x = __expf(v0.x - mx); v0.y = __expf(v0.y - mx);
    v0.z = __expf(v0.z - mx); v0.w = __expf(v0.w - mx);
    v1.x = __expf(v1.x - mx); v1.y = __expf(v1.y - mx);
    v1.z = __expf(v1.z - mx); v1.w = __expf(v1.w - mx);

    float sm_ = v0.x + v0.y + v0.z + v0.w + v1.x + v1.y + v1.z + v1.w;
#pragma unroll
    for (int off = 16; off > 0; off >>= 1)
        sm_ += __shfl_xor_sync(0xffffffffu, sm_, off);
    if ((tid & 31) == 0) red[tid >> 5] = sm_;
    __syncthreads();
    if (tid < 32) {
        float t = (tid < 8) ? red[tid] : 0.0f;
#pragma unroll
        for (int off = 4; off > 0; off >>= 1)
            t += __shfl_xor_sync(0xffffffffu, t, off);
        if (tid == 0) red[0] = t;
    }
    __syncthreads();
    float inv = 1.0f / red[0];

    v0.x *= inv; v0.y *= inv; v0.z *= inv; v0.w *= inv;
    v1.x *= inv; v1.y *= inv; v1.z *= inv; v1.w *= inv;
    *(float4*)(row + tid * 4) = v0;
    *(float4*)(row + 1024 + tid * 4) = v1;
}

// ---------------------------------------------------------------------------
extern "C" void kernel_launch(void* const* d_in, const int* in_sizes, int n_in,
                              void* d_out, int out_size)
{
    const float* x     = (const float*)d_in[0];   // [8,2048,768]
    const float* w_qkv = (const float*)d_in[1];   // [768,2304]
    const float* b_qkv = (const float*)d_in[2];   // [2304]
    const float* w_out = (const float*)d_in[3];   // [768,768]
    const float* b_out = (const float*)d_in[4];   // [768]
    float* out = (float*)d_out;                   // [8,2048,768]

    float *qkv_p, *sc_p, *att_p, *wqT, *woT, *vT;
    cudaGetSymbolAddress((void**)&qkv_p, g_qkv);
    cudaGetSymbolAddress((void**)&sc_p, g_scores);
    cudaGetSymbolAddress((void**)&att_p, g_att);
    cudaGetSymbolAddress((void**)&wqT, g_wqkvT);
    cudaGetSymbolAddress((void**)&woT, g_woutT);
    cudaGetSymbolAddress((void**)&vT, g_vT);

    const long long sQKV = (long long)SEQ * QKVO;
    const long long sS   = (long long)SEQ * SEQ;
    const long long sO   = (long long)SEQ * DIM;
    const long long sVT  = (long long)DIM * SEQ;

    // 0a) w_qkv [768,2304] -> w_qkvT [2304,768]
    transpose_kernel<<<dim3(QKVO / 32, DIM / 32, 1), 256>>>(
        w_qkv, wqT, QKVO, DIM, 0, 0);
    // 0b) w_out [768,768] -> w_outT
    transpose_kernel<<<dim3(DIM / 32, DIM / 32, 1), 256>>>(
        w_out, woT, DIM, DIM, 0, 0);

    // 1) QKV projection: x @ w_qkvT^T + b_qkv   (M=16384, N=2304, K=768)
    gemm_nt<<<dim3(QKVO / 128, BT / 128, 1), 256>>>(
        x, wqT, b_qkv, qkv_p, DIM, DIM, DIM, QKVO, 1.0f, 0, 0, 0);

    // 1b) V (rows of qkv, +1536) -> vT [768,2048] per batch
    transpose_kernel<<<dim3(DIM / 32, SEQ / 32, NB), 256>>>(
        qkv_p + 2 * DIM, vT, QKVO, SEQ, sQKV, sVT);

    // 2) S = 0.125 * Q @ K^T per batch (M=N=2048, K=768)
    gemm_nt<<<dim3(SEQ / 128, SEQ / 128, NB), 256>>>(
        qkv_p, qkv_p + DIM, nullptr, sc_p, DIM, QKVO, QKVO, SEQ,
        SCALE, sQKV, sQKV, sS);

    // 3) Row softmax in place
    softmax_kernel<<<NB * SEQ, 256>>>(sc_p);

    // 4) O = P @ vT^T per batch (M=2048, N=768, K=2048)
    gemm_nt<<<dim3(DIM / 128, SEQ / 128, NB), 256>>>(
        sc_p, vT, nullptr, att_p, SEQ, SEQ, SEQ, DIM, 1.0f, sS, sVT, sO);

    // 5) Output projection: att @ w_outT^T + b_out (M=16384, N=768, K=768)
    gemm_nt<<<dim3(DIM / 128, BT / 128, 1), 256>>>(
        att_p, woT, b_out, out, DIM, DIM, DIM, DIM, 1.0f, 0, 0, 0);
}

// round 17
// speedup vs baseline: 2.1116x; 1.2399x over previous
#include <cuda_runtime.h>
#include <cuda_bf16.h>
#include <stdint.h>

// B=8, T=2048, D=768, QKV_OUT=2304. Single-head attention over full 768 dims,
// scale 1/sqrt(64)=0.125. All GEMMs NT on mma.sync bf16 (split hi/lo 3-pass),
// ldmatrix fragments, 256thr x 2CTA/SM, warp tile 64x32, BK=32, 40KB static
// smem (R10 baseline). R17: pass-major MMA order (break acc RAW chains) +
// bf16x2 split2. NO register prefetch (R16 spilled).
#define BT 16384
#define DIM 768
#define QKVO 2304
#define SEQ 2048
#define NB 8
#define SCALE 0.125f

__device__ float g_qkv[(size_t)BT * QKVO];          // 16384 x 2304 (q|k|v)
__device__ float g_scores[(size_t)NB * SEQ * SEQ];  // 8 x 2048 x 2048
__device__ float g_att[(size_t)BT * DIM];           // 16384 x 768
__device__ float g_wqkvT[(size_t)QKVO * DIM];       // 2304 x 768
__device__ float g_woutT[(size_t)DIM * DIM];        // 768 x 768
__device__ float g_vT[(size_t)NB * DIM * SEQ];      // 8 x 768 x 2048

// split pair (x lower-k, y upper-k) -> packed hi word, lo word.
// cvt.rn.bf16x2.f32 packs with RN rounding = __float2bfloat16 (bit-identical).
__device__ __forceinline__ void split2(float x, float y, uint32_t& h, uint32_t& l) {
    asm("cvt.rn.bf16x2.f32 %0, %1, %2;" : "=r"(h) : "f"(y), "f"(x));
    float hx = __uint_as_float(h << 16);
    float hy = __uint_as_float(h & 0xFFFF0000u);
    asm("cvt.rn.bf16x2.f32 %0, %1, %2;" : "=r"(l) : "f"(y - hy), "f"(x - hx));
}
__device__ __forceinline__ void mma_bf16(float* d, const uint32_t* a, const uint32_t* b) {
    asm volatile(
        "mma.sync.aligned.m16n8k16.row.col.f32.bf16.bf16.f32 "
        "{%0,%1,%2,%3}, {%4,%5,%6,%7}, {%8,%9}, {%0,%1,%2,%3};"
        : "+f"(d[0]), "+f"(d[1]), "+f"(d[2]), "+f"(d[3])
        : "r"(a[0]), "r"(a[1]), "r"(a[2]), "r"(a[3]), "r"(b[0]), "r"(b[1]));
}
#define LDSM_X4(r0, r1, r2, r3, addr) \
    asm volatile("ldmatrix.sync.aligned.m8n8.x4.shared.b16 {%0,%1,%2,%3}, [%4];" \
        : "=r"(r0), "=r"(r1), "=r"(r2), "=r"(r3) : "r"(addr))

// Plane layout: [row][k] rows of 40 bf16 (80 B). Planes: Ah | Al | Bh | Bl.
#define PLANE 10240
#define ROWB 80

// ---------------------------------------------------------------------------
// NT GEMM: C[M,N] = alpha * A[M,K] @ B[N,K]^T (+bias). Batched via grid.z.
// BM=BN=128, BK=32. 256 threads = 8 warps (2M x 4N), warp tile 64x32.
// Single smem buffer (40KB static), 2 CTAs/SM.
// ---------------------------------------------------------------------------
__global__ __launch_bounds__(256, 2)
void gemm_nt(const float* __restrict__ A, const float* __restrict__ B,
             const float* __restrict__ bias, float* __restrict__ C,
             int K, int lda, int ldb, int ldc, float alpha,
             long long sA, long long sB, long long sC)
{
    __shared__ __align__(16) char smem[4 * PLANE];

    const int tid = threadIdx.x;
    const int lane = tid & 31;
    const int wid = tid >> 5;
    const int wm = (wid >> 2) * 64;     // 0 / 64
    const int wn = (wid & 3) * 32;      // 0/32/64/96
    const int lr = lane >> 2;           // 0..7
    const int lc = lane & 3;            // 0..3

    const uint32_t sbase = (uint32_t)__cvta_generic_to_shared(smem);
    const int lm_i = lane & 7, lm_j = lane >> 3;
    const uint32_t laneoff =
        (uint32_t)((lm_i + (lm_j & 1) * 8) * ROWB + (lm_j >> 1) * 16);

    const float* Ap = A + (size_t)blockIdx.z * sA + (size_t)blockIdx.y * 128 * lda;
    const float* Bp = B + (size_t)blockIdx.z * sB + (size_t)blockIdx.x * 128 * ldb;
    float* Cb = C + (size_t)blockIdx.z * sC;

    // loader: thread -> row (0..127), col quad base (0 or 16 floats)
    const int ld_row = tid >> 1;
    const int ld_c0 = (tid & 1) * 16;

    float acc[4][4][4];
#pragma unroll
    for (int i = 0; i < 4; i++)
#pragma unroll
        for (int j = 0; j < 4; j++)
#pragma unroll
            for (int q = 0; q < 4; q++) acc[i][j][q] = 0.0f;

    const int nc = K >> 5;
    for (int ch = 0; ch < nc; ch++) {
        const int k0 = ch << 5;
        __syncthreads();   // previous compute done before overwrite
        // ---- load + split A (rows=m) and B (rows=n) into hi/lo planes ----
        {
            const float* ar = Ap + (size_t)ld_row * lda + k0 + ld_c0;
            const float* br = Bp + (size_t)ld_row * ldb + k0 + ld_c0;
            char* Ah = smem;
            char* Al = smem + PLANE;
            char* Bh = smem + 2 * PLANE;
            char* Bl = smem + 3 * PLANE;
            const int wo = ld_row * ROWB + ld_c0 * 2;   // byte offset
#pragma unroll
            for (int q = 0; q < 4; q++) {
                float4 v = *(const float4*)(ar + q * 4);
                uint2 h, l;
                split2(v.x, v.y, h.x, l.x);
                split2(v.z, v.w, h.y, l.y);
                *(uint2*)(Ah + wo + q * 8) = h;
                *(uint2*)(Al + wo + q * 8) = l;
            }
#pragma unroll
            for (int q = 0; q < 4; q++) {
                float4 v = *(const float4*)(br + q * 4);
                uint2 h, l;
                split2(v.x, v.y, h.x, l.x);
                split2(v.z, v.w, h.y, l.y);
                *(uint2*)(Bh + wo + q * 8) = h;
                *(uint2*)(Bl + wo + q * 8) = l;
            }
        }
        __syncthreads();

        // ---- compute: 2 k16 steps ----
#pragma unroll
        for (int ks = 0; ks < 2; ks++) {
            const uint32_t kb = (uint32_t)(ks * 32);   // 16 bf16 = 32 B
            uint32_t bh[4][2], bl[4][2];
#pragma unroll
            for (int q = 0; q < 2; q++) {
                uint32_t ba = sbase + 2 * PLANE
                            + (uint32_t)((wn + q * 16) * ROWB) + laneoff + kb;
                uint32_t r0, r1, r2, r3;
                LDSM_X4(r0, r1, r2, r3, ba);
                bh[q * 2][0] = r0; bh[q * 2 + 1][0] = r1;
                bh[q * 2][1] = r2; bh[q * 2 + 1][1] = r3;
                LDSM_X4(r0, r1, r2, r3, ba + PLANE);
                bl[q * 2][0] = r0; bl[q * 2 + 1][0] = r1;
                bl[q * 2][1] = r2; bl[q * 2 + 1][1] = r3;
            }
#pragma unroll
            for (int im = 0; im < 4; im++) {
                uint32_t aa = sbase + (uint32_t)((wm + im * 16) * ROWB)
                            + laneoff + kb;
                uint32_t ah[4], al[4];
                LDSM_X4(ah[0], ah[1], ah[2], ah[3], aa);
                LDSM_X4(al[0], al[1], al[2], al[3], aa + PLANE);
                // Pass-major order: consecutive MMAs hit different accs
                // (RAW distance 4) instead of 3 back-to-back on one acc.
#pragma unroll
                for (int jn = 0; jn < 4; jn++)
                    mma_bf16(acc[im][jn], ah, bh[jn]);   // hi*hi
#pragma unroll
                for (int jn = 0; jn < 4; jn++)
                    mma_bf16(acc[im][jn], ah, bl[jn]);   // hi*lo
#pragma unroll
                for (int jn = 0; jn < 4; jn++)
                    mma_bf16(acc[im][jn], al, bh[jn]);   // lo*hi
            }
        }
    }

    // ---- epilogue (verified m16n8 C mapping) ----
#pragma unroll
    for (int im = 0; im < 4; im++) {
        int r0 = blockIdx.y * 128 + wm + im * 16 + lr;
#pragma unroll
        for (int jn = 0; jn < 4; jn++) {
            int c0 = blockIdx.x * 128 + wn + jn * 8 + 2 * lc;
            float bx = 0.0f, by = 0.0f;
            if (bias) { bx = bias[c0]; by = bias[c0 + 1]; }
            float2 v0, v1;
            v0.x = alpha * acc[im][jn][0] + bx;
            v0.y = alpha * acc[im][jn][1] + by;
            v1.x = alpha * acc[im][jn][2] + bx;
            v1.y = alpha * acc[im][jn][3] + by;
            *(float2*)(Cb + (size_t)r0 * ldc + c0) = v0;
            *(float2*)(Cb + (size_t)(r0 + 8) * ldc + c0) = v1;
        }
    }
}

// ---------------------------------------------------------------------------
// Batched strided 32x32 tiled transpose: dst[c][r] = src[r][c].
// ---------------------------------------------------------------------------
__global__ __launch_bounds__(256)
void transpose_kernel(const float* __restrict__ src, float* __restrict__ dst,
                      int lds, int ldd, long long sS, long long sD)
{
    __shared__ float t[32][33];
    src += (size_t)blockIdx.z * sS;
    dst += (size_t)blockIdx.z * sD;
    int r0 = blockIdx.y * 32, c0 = blockIdx.x * 32;
    int tx = threadIdx.x & 31, ty = threadIdx.x >> 5;   // 32 x 8
#pragma unroll
    for (int i = ty; i < 32; i += 8)
        t[i][tx] = src[(size_t)(r0 + i) * lds + c0 + tx];
    __syncthreads();
#pragma unroll
    for (int i = ty; i < 32; i += 8)
        dst[(size_t)(c0 + i) * ldd + r0 + tx] = t[tx][i];
}

// ---------------------------------------------------------------------------
// Row softmax in place: 16384 rows x 2048 cols. One block (256 thr) per row.
// ---------------------------------------------------------------------------
__global__ __launch_bounds__(256)
void softmax_kernel(float* __restrict__ S)
{
    __shared__ float red[8];
    int tid = threadIdx.x;
    float* row = S + (size_t)blockIdx.x * SEQ;

    float4 v0 = *(const float4*)(row + tid * 4);
    float4 v1 = *(const float4*)(row + 1024 + tid * 4);

    float mx = fmaxf(fmaxf(fmaxf(v0.x, v0.y), fmaxf(v0.z, v0.w)),
                     fmaxf(fmaxf(v1.x, v1.y), fmaxf(v1.z, v1.w)));
#pragma unroll
    for (int off = 16; off > 0; off >>= 1)
        mx = fmaxf(mx, __shfl_xor_sync(0xffffffffu, mx, off));
    if ((tid & 31) == 0) red[tid >> 5] = mx;
    __syncthreads();
    if (tid < 32) {
        float t = (tid < 8) ? red[tid] : -1e30f;
#pragma unroll
        for (int off = 4; off > 0; off >>= 1)
            t = fmaxf(t, __shfl_xor_sync(0xffffffffu, t, off));
        if (tid == 0) red[0] = t;
    }
    __syncthreads();
    mx = red[0];

    v0.x = __expf(v0.x - mx); v0.y = __expf(v0.y - mx);
    v0.z = __expf(v0.z - mx); v0.w = __expf(v0.w - mx);
    v1.x = __expf(v1.x - mx); v1.y = __expf(v1.y - mx);
    v1.z = __expf(v1.z - mx); v1.w = __expf(v1.w - mx);

    float sm_ = v0.x + v0.y + v0.z + v0.w + v1.x + v1.y + v1.z + v1.w;
#pragma unroll
    for (int off = 16; off > 0; off >>= 1)
        sm_ += __shfl_xor_sync(0xffffffffu, sm_, off);
    if ((tid & 31) == 0) red[tid >> 5] = sm_;
    __syncthreads();
    if (tid < 32) {
        float t = (tid < 8) ? red[tid] : 0.0f;
#pragma unroll
        for (int off = 4; off > 0; off >>= 1)
            t += __shfl_xor_sync(0xffffffffu, t, off);
        if (tid == 0) red[0] = t;
    }
    __syncthreads();
    float inv = 1.0f / red[0];

    v0.x *= inv; v0.y *= inv; v0.z *= inv; v0.w *= inv;
    v1.x *= inv; v1.y *= inv; v1.z *= inv; v1.w *= inv;
    *(float4*)(row + tid * 4) = v0;
    *(float4*)(row + 1024 + tid * 4) = v1;
}

// ---------------------------------------------------------------------------
extern "C" void kernel_launch(void* const* d_in, const int* in_sizes, int n_in,
                              void* d_out, int out_size)
{
    const float* x     = (const float*)d_in[0];   // [8,2048,768]
    const float* w_qkv = (const float*)d_in[1];   // [768,2304]
    const float* b_qkv = (const float*)d_in[2];   // [2304]
    const float* w_out = (const float*)d_in[3];   // [768,768]
    const float* b_out = (const float*)d_in[4];   // [768]
    float* out = (float*)d_out;                   // [8,2048,768]

    float *qkv_p, *sc_p, *att_p, *wqT, *woT, *vT;
    cudaGetSymbolAddress((void**)&qkv_p, g_qkv);
    cudaGetSymbolAddress((void**)&sc_p, g_scores);
    cudaGetSymbolAddress((void**)&att_p, g_att);
    cudaGetSymbolAddress((void**)&wqT, g_wqkvT);
    cudaGetSymbolAddress((void**)&woT, g_woutT);
    cudaGetSymbolAddress((void**)&vT, g_vT);

    const long long sQKV = (long long)SEQ * QKVO;
    const long long sS   = (long long)SEQ * SEQ;
    const long long sO   = (long long)SEQ * DIM;
    const long long sVT  = (long long)DIM * SEQ;

    // 0a) w_qkv [768,2304] -> w_qkvT [2304,768]
    transpose_kernel<<<dim3(QKVO / 32, DIM / 32, 1), 256>>>(
        w_qkv, wqT, QKVO, DIM, 0, 0);
    // 0b) w_out [768,768] -> w_outT
    transpose_kernel<<<dim3(DIM / 32, DIM / 32, 1), 256>>>(
        w_out, woT, DIM, DIM, 0, 0);

    // 1) QKV projection: x @ w_qkvT^T + b_qkv   (M=16384, N=2304, K=768)
    gemm_nt<<<dim3(QKVO / 128, BT / 128, 1), 256>>>(
        x, wqT, b_qkv, qkv_p, DIM, DIM, DIM, QKVO, 1.0f, 0, 0, 0);

    // 1b) V (rows of qkv, +1536) -> vT [768,2048] per batch
    transpose_kernel<<<dim3(DIM / 32, SEQ / 32, NB), 256>>>(
        qkv_p + 2 * DIM, vT, QKVO, SEQ, sQKV, sVT);

    // 2) S = 0.125 * Q @ K^T per batch (M=N=2048, K=768)
    gemm_nt<<<dim3(SEQ / 128, SEQ / 128, NB), 256>>>(
        qkv_p, qkv_p + DIM, nullptr, sc_p, DIM, QKVO, QKVO, SEQ,
        SCALE, sQKV, sQKV, sS);

    // 3) Row softmax in place
    softmax_kernel<<<NB * SEQ, 256>>>(sc_p);

    // 4) O = P @ vT^T per batch (M=2048, N=768, K=2048)
    gemm_nt<<<dim3(DIM / 128, SEQ / 128, NB), 256>>>(
        sc_p, vT, nullptr, att_p, SEQ, SEQ, SEQ, DIM, 1.0f, sS, sVT, sO);

    // 5) Output projection: att @ w_outT^T + b_out (M=16384, N=768, K=768)
    gemm_nt<<<dim3(DIM / 128, BT / 128, 1), 256>>>(
        att_p, woT, b_out, out, DIM, DIM, DIM, DIM, 1.0f, 0, 0, 0);
}